// round 9
// baseline (speedup 1.0000x reference)
#include <cuda_runtime.h>
#include <cuda_bf16.h>
#include <mma.h>
#include <cstdint>
#include <cstdio>

using namespace nvcuda;

// ---------------- Problem constants ----------------
#define T_LEN   1024
#define HID     1024
#define H_HEADS 32
#define P_DIM   64
#define N_STATE 128
#define NL      15
#define KCONV   4
#define INTER   2048          // H*P
#define CONV_DIM 2304         // INTER + 2*N
#define PROJ    4864          // INTER + CONV_DIM + H*(NL+1)
#define DT_OFF  4352          // INTER + CONV_DIM
#define EPSNRM  1e-5f

// ---------------- Scratch (device globals; no allocation allowed) ----------------
__device__ float g_zx[T_LEN * PROJ];        // in_proj output (bias fused in consumers)
__device__ float g_x[T_LEN * INTER];        // conv+silu x part (unscaled)
__device__ float g_dt[T_LEN * H_HEADS];     // softplus dt, [t][h]
__device__ float g_g[H_HEADS * T_LEN];      // per-step log decay, [h][t]
__device__ float g_cg[H_HEADS * T_LEN];     // cumsum, [h][t]
__device__ float g_Ls[T_LEN * H_HEADS * NL];// level scales [t][h][l]
__device__ float g_scores[T_LEN * T_LEN];   // C·B^T (head-independent, G=1)
__device__ float g_y[T_LEN * INTER];        // attention output + D residual

// bf16 hi/lo split operands for tensor-core GEMMs
__device__ __nv_bfloat16 g_hsh[T_LEN * HID],  g_hsl[T_LEN * HID];
__device__ __nv_bfloat16 g_w1h[PROJ * HID],   g_w1l[PROJ * HID];
__device__ __nv_bfloat16 g_w2h[HID * INTER],  g_w2l[HID * INTER];
__device__ __nv_bfloat16 g_Bh[T_LEN * N_STATE], g_Bl[T_LEN * N_STATE];
__device__ __nv_bfloat16 g_Ch[T_LEN * N_STATE], g_Cl[T_LEN * N_STATE];
__device__ __nv_bfloat16 g_ynh[T_LEN * INTER],  g_ynl[T_LEN * INTER];

__device__ __forceinline__ float softplus_f(float x) {
    return (x > 20.f) ? x : log1pf(expf(x));
}
__device__ __forceinline__ float silu_f(float x) {
    return x / (1.f + expf(-x));
}
__device__ __forceinline__ void split_bf16(float x, __nv_bfloat16& h, __nv_bfloat16& l) {
    h = __float2bfloat16(x);
    l = __float2bfloat16(x - __bfloat162float(h));
}

#define CP_ASYNC16(smem_u32, gptr) \
    asm volatile("cp.async.cg.shared.global [%0], [%1], 16;\n" :: "r"(smem_u32), "l"(gptr))
#define CP_COMMIT() asm volatile("cp.async.commit_group;\n" ::: "memory")
#define CP_WAIT(n)  asm volatile("cp.async.wait_group %0;\n" :: "n"(n) : "memory")

// ---------------- fp32 -> bf16 hi/lo split ----------------
__global__ void split_kernel(const float* __restrict__ src,
                             __nv_bfloat16* __restrict__ hi,
                             __nv_bfloat16* __restrict__ lo, int n) {
    int i = blockIdx.x * blockDim.x + threadIdx.x;
    if (i < n) {
        __nv_bfloat16 h, l;
        split_bf16(src[i], h, l);
        hi[i] = h; lo[i] = l;
    }
}

// ---------------- bias add (final output epilogue) ----------------
__global__ void bias_add_kernel(float* __restrict__ C, const float* __restrict__ bias,
                                int N, int total) {
    int i = blockIdx.x * blockDim.x + threadIdx.x;
    if (i < total) C[i] += bias[i % N];
}

// ---------------- Tensor-core NT GEMM, split-bf16 x3, 64x64 warp tiles ----------------
// C[m,n] = sum_k A[m,k]*B[n,k], A=Ah+Al, B=Bh+Bl; C ~= Ah*Bh + Al*Bh + Ah*Bl.
// Block tile BM x 128, BM threads (BM/32 warps, each 64x64). K-tile 32, 2-stage cp.async.
// Dynamic smem layout per stage (bf16 elems): [Ah BM*40][Al BM*40][Bh 128*40][Bl 128*40].
template <int BM>
__global__ __launch_bounds__(BM, 1)
void gemm_wmma(const __nv_bfloat16* __restrict__ Ah, const __nv_bfloat16* __restrict__ Al,
               const __nv_bfloat16* __restrict__ Bh, const __nv_bfloat16* __restrict__ Bl,
               float* __restrict__ C, int M, int N, int K) {
    constexpr int NTHR = BM;
    constexpr int WMC  = BM / 64;                 // warps along m
    constexpr int STG_A = BM * 40;                // bf16 elems
    constexpr int STG_B = 128 * 40;
    constexpr int STAGE = 2 * STG_A + 2 * STG_B;

    extern __shared__ __nv_bfloat16 smem[];
    const int tid = threadIdx.x;
    const int warp = tid >> 5;
    const int bm = blockIdx.y * BM, bn = blockIdx.x * 128;
    const int wm = (warp % WMC) * 64;
    const int wn = (warp / WMC) * 64;

    wmma::fragment<wmma::accumulator, 16, 16, 16, float> acc[4][4];
#pragma unroll
    for (int i = 0; i < 4; i++)
#pragma unroll
        for (int j = 0; j < 4; j++) wmma::fill_fragment(acc[i][j], 0.f);

    auto load_stage = [&](int k0, int buf) {
        __nv_bfloat16* st = smem + buf * STAGE;
#pragma unroll
        for (int i = tid; i < BM * 4; i += NTHR) {
            const int r = i >> 2, c = (i & 3) * 8;
            const size_t off = (size_t)(bm + r) * K + k0 + c;
            CP_ASYNC16((unsigned)__cvta_generic_to_shared(st + r * 40 + c), Ah + off);
            CP_ASYNC16((unsigned)__cvta_generic_to_shared(st + STG_A + r * 40 + c), Al + off);
        }
#pragma unroll
        for (int i = tid; i < 128 * 4; i += NTHR) {
            const int r = i >> 2, c = (i & 3) * 8;
            const size_t off = (size_t)(bn + r) * K + k0 + c;
            CP_ASYNC16((unsigned)__cvta_generic_to_shared(st + 2 * STG_A + r * 40 + c), Bh + off);
            CP_ASYNC16((unsigned)__cvta_generic_to_shared(st + 2 * STG_A + STG_B + r * 40 + c), Bl + off);
        }
    };

    load_stage(0, 0);
    CP_COMMIT();

    const int nt = K >> 5;
    for (int kt = 0; kt < nt; kt++) {
        const int buf = kt & 1;
        if (kt + 1 < nt) {
            load_stage((kt + 1) << 5, buf ^ 1);
            CP_COMMIT();
            CP_WAIT(1);
        } else {
            CP_WAIT(0);
        }
        __syncthreads();
        const __nv_bfloat16* st = smem + buf * STAGE;
        const __nv_bfloat16* sa_h = st;
        const __nv_bfloat16* sa_l = st + STG_A;
        const __nv_bfloat16* sb_h = st + 2 * STG_A;
        const __nv_bfloat16* sb_l = st + 2 * STG_A + STG_B;
#pragma unroll
        for (int ks = 0; ks < 32; ks += 16) {
            wmma::fragment<wmma::matrix_b, 16, 16, 16, __nv_bfloat16, wmma::col_major> bh[4], bl[4];
#pragma unroll
            for (int j = 0; j < 4; j++) {
                wmma::load_matrix_sync(bh[j], sb_h + (wn + 16 * j) * 40 + ks, 40);
                wmma::load_matrix_sync(bl[j], sb_l + (wn + 16 * j) * 40 + ks, 40);
            }
#pragma unroll
            for (int i = 0; i < 4; i++) {
                wmma::fragment<wmma::matrix_a, 16, 16, 16, __nv_bfloat16, wmma::row_major> ah, al;
                wmma::load_matrix_sync(ah, sa_h + (wm + 16 * i) * 40 + ks, 40);
                wmma::load_matrix_sync(al, sa_l + (wm + 16 * i) * 40 + ks, 40);
#pragma unroll
                for (int j = 0; j < 4; j++) {
                    wmma::mma_sync(acc[i][j], ah, bh[j], acc[i][j]);
                    wmma::mma_sync(acc[i][j], al, bh[j], acc[i][j]);
                    wmma::mma_sync(acc[i][j], ah, bl[j], acc[i][j]);
                }
            }
        }
        __syncthreads();
    }
#pragma unroll
    for (int i = 0; i < 4; i++)
#pragma unroll
        for (int j = 0; j < 4; j++)
            wmma::store_matrix_sync(C + (size_t)(bm + wm + 16 * i) * N + bn + wn + 16 * j,
                                    acc[i][j], N, wmma::mem_row_major);
}

#define SMEM_BM256 ((2 * (2 * 256 * 40 + 2 * 128 * 40)) * 2)
#define SMEM_BM128 ((2 * (2 * 128 * 40 + 2 * 128 * 40)) * 2)

// ---------------- Depthwise causal conv (K=4) + SiLU + split (b1 fused) ----------------
__global__ void conv_silu_kernel(const float* __restrict__ conv_w,
                                 const float* __restrict__ b1) {
    int idx = blockIdx.x * blockDim.x + threadIdx.x;
    if (idx >= T_LEN * CONV_DIM) return;
    int t = idx / CONV_DIM;
    int c = idx % CONV_DIM;
    const float bias = b1[INTER + c];
    float acc = 0.f;
#pragma unroll
    for (int w = 0; w < KCONV; w++) {
        int ts = t - (KCONV - 1) + w;
        if (ts >= 0)
            acc = fmaf(g_zx[(size_t)ts * PROJ + INTER + c] + bias, conv_w[c * KCONV + w], acc);
    }
    float s = silu_f(acc);
    if (c < INTER) {
        g_x[(size_t)t * INTER + c] = s;
    } else if (c < INTER + N_STATE) {
        __nv_bfloat16 h, l; split_bf16(s, h, l);
        int o = t * N_STATE + (c - INTER);
        g_Bh[o] = h; g_Bl[o] = l;
    } else {
        __nv_bfloat16 h, l; split_bf16(s, h, l);
        int o = t * N_STATE + (c - INTER - N_STATE);
        g_Ch[o] = h; g_Cl[o] = l;
    }
}

// ---------------- dt / g / Ls prep (b1 fused) ----------------
__global__ void prep_kernel(const float* __restrict__ dt_bias,
                            const float* __restrict__ A_log,
                            const float* __restrict__ L_param,
                            const float* __restrict__ b1) {
    int t = blockIdx.x;
    const float* row = g_zx + (size_t)t * PROJ + DT_OFF;
    const float* brow = b1 + DT_OFF;
    for (int i = threadIdx.x; i < H_HEADS; i += blockDim.x) {
        float d = softplus_f(row[i] + brow[i] + dt_bias[i]);
        g_dt[t * H_HEADS + i] = d;
        g_g[i * T_LEN + t] = -expf(A_log[i]) * d;
    }
    for (int i = threadIdx.x; i < H_HEADS * NL; i += blockDim.x) {
        g_Ls[(size_t)t * (H_HEADS * NL) + i] =
            softplus_f(L_param[i] * (row[H_HEADS + i] + brow[H_HEADS + i]));
    }
}

// ---------------- inclusive scan of g over t, per head ----------------
__global__ __launch_bounds__(1024)
void scan_kernel() {
    __shared__ float sh[T_LEN];
    int h = blockIdx.x;
    int t = threadIdx.x;
    sh[t] = g_g[h * T_LEN + t];
    __syncthreads();
    for (int off = 1; off < T_LEN; off <<= 1) {
        float add = (t >= off) ? sh[t - off] : 0.f;
        __syncthreads();
        sh[t] += add;
        __syncthreads();
    }
    g_cg[h * T_LEN + t] = sh[t];
}

// ---------------- Attention: per (head, t-tile of 64) ----------------
__global__ __launch_bounds__(256)
void attn_kernel(const int* __restrict__ lvl, const float* __restrict__ Dp) {
    const int h = blockIdx.y;
    const int t0 = blockIdx.x * 64;
    __shared__ float s_w[64][65];
    __shared__ float s_v[64][65];
    __shared__ float s_cgt[64];
    __shared__ float s_cgs[64];
    __shared__ float s_Lst[64][16];
    const int tid = threadIdx.x;

    if (tid < 64) s_cgt[tid] = g_cg[h * T_LEN + t0 + tid];
    for (int i = tid; i < 64 * NL; i += 256) {
        int r = i / NL, l = i % NL;
        s_Lst[r][l] = g_Ls[((size_t)(t0 + r) * H_HEADS + h) * NL + l];
    }

    float acc[4][4];
#pragma unroll
    for (int i = 0; i < 4; i++)
#pragma unroll
        for (int j = 0; j < 4; j++) acc[i][j] = 0.f;

    const int tr = (tid >> 4) << 2;
    const int tc = (tid & 15) << 2;

    for (int s0 = 0; s0 <= t0; s0 += 64) {
        __syncthreads();
        if (s0 < t0) {
            float maxld = g_cg[h * T_LEN + t0] - g_cg[h * T_LEN + s0 + 63];
            if (maxld < -30.f) continue;
        }
        for (int i = tid; i < 64 * 64; i += 256) {
            int r = i >> 6, c = i & 63;
            s_w[r][c] = g_scores[(size_t)(t0 + r) * T_LEN + s0 + c];
        }
        for (int i = tid; i < 64 * 64; i += 256) {
            int r = i >> 6, p = i & 63;
            s_v[r][p] = g_x[(size_t)(s0 + r) * INTER + h * P_DIM + p] *
                        g_dt[(s0 + r) * H_HEADS + h];
        }
        if (tid < 64) s_cgs[tid] = g_cg[h * T_LEN + s0 + tid];
        __syncthreads();
        for (int i = tid; i < 64 * 64; i += 256) {
            int r = i >> 6, c = i & 63;
            int tg = t0 + r, sg = s0 + c;
            float w = 0.f;
            if (sg <= tg) {
                int L = lvl[(size_t)tg * T_LEN + sg];
                w = s_w[r][c] * __expf(s_cgt[r] - s_cgs[c]) * s_Lst[r][L];
            }
            s_w[r][c] = w;
        }
        __syncthreads();
#pragma unroll 8
        for (int k = 0; k < 64; k++) {
            float a[4], b[4];
#pragma unroll
            for (int i = 0; i < 4; i++) a[i] = s_w[tr + i][k];
#pragma unroll
            for (int j = 0; j < 4; j++) b[j] = s_v[k][tc + j];
#pragma unroll
            for (int i = 0; i < 4; i++)
#pragma unroll
                for (int j = 0; j < 4; j++)
                    acc[i][j] = fmaf(a[i], b[j], acc[i][j]);
        }
    }
    const float Dh = Dp[h];
#pragma unroll
    for (int i = 0; i < 4; i++) {
        int tg = t0 + tr + i;
#pragma unroll
        for (int j = 0; j < 4; j++) {
            int col = h * P_DIM + tc + j;
            g_y[(size_t)tg * INTER + col] =
                acc[i][j] + g_x[(size_t)tg * INTER + col] * Dh;
        }
    }
}

// ---------------- gated RMSNorm (b1 fused into z), bf16 hi/lo out ----------------
__global__ __launch_bounds__(256)
void gated_norm_kernel(const float* __restrict__ rmsw, const float* __restrict__ b1) {
    const int t = blockIdx.x;
    __shared__ float red[8];
    float vals[8];
    float local = 0.f;
#pragma unroll
    for (int i = 0; i < 8; i++) {
        int c = threadIdx.x + i * 256;
        float z = g_zx[(size_t)t * PROJ + c] + b1[c];
        float yv = g_y[(size_t)t * INTER + c];
        float gv = yv * silu_f(z);
        vals[i] = gv;
        local = fmaf(gv, gv, local);
    }
#pragma unroll
    for (int off = 16; off > 0; off >>= 1)
        local += __shfl_xor_sync(0xffffffffu, local, off);
    if ((threadIdx.x & 31) == 0) red[threadIdx.x >> 5] = local;
    __syncthreads();
    if (threadIdx.x < 8) {
        float v = red[threadIdx.x];
#pragma unroll
        for (int off = 4; off > 0; off >>= 1)
            v += __shfl_xor_sync(0xffu, v, off);
        if (threadIdx.x == 0) red[0] = v;
    }
    __syncthreads();
    const float inv = rsqrtf(red[0] / (float)INTER + EPSNRM);
#pragma unroll
    for (int i = 0; i < 8; i++) {
        int c = threadIdx.x + i * 256;
        float v = vals[i] * inv * rmsw[c];
        __nv_bfloat16 h, l; split_bf16(v, h, l);
        g_ynh[(size_t)t * INTER + c] = h;
        g_ynl[(size_t)t * INTER + c] = l;
    }
}

// ---------------- Launch ----------------
extern "C" void kernel_launch(void* const* d_in, const int* in_sizes, int n_in,
                              void* d_out, int out_size) {
    const float* hs    = (const float*)d_in[0];
    const float* w1    = (const float*)d_in[1];
    const float* b1    = (const float*)d_in[2];
    const float* cw    = (const float*)d_in[3];
    const float* dtb   = (const float*)d_in[4];
    const float* alog  = (const float*)d_in[5];
    const float* lpar  = (const float*)d_in[6];
    const float* Dp    = (const float*)d_in[7];
    const float* rmsw  = (const float*)d_in[8];
    const float* w2    = (const float*)d_in[9];
    const float* b2    = (const float*)d_in[10];
    const int*   lvl   = (const int*)d_in[11];
    float* out = (float*)d_out;

    float *zx, *scores;
    __nv_bfloat16 *hsh, *hsl, *w1h, *w1l, *w2h, *w2l, *Bh, *Bl, *Ch, *Cl, *ynh, *ynl;
    cudaGetSymbolAddress((void**)&zx, g_zx);
    cudaGetSymbolAddress((void**)&scores, g_scores);
    cudaGetSymbolAddress((void**)&hsh, g_hsh);  cudaGetSymbolAddress((void**)&hsl, g_hsl);
    cudaGetSymbolAddress((void**)&w1h, g_w1h);  cudaGetSymbolAddress((void**)&w1l, g_w1l);
    cudaGetSymbolAddress((void**)&w2h, g_w2h);  cudaGetSymbolAddress((void**)&w2l, g_w2l);
    cudaGetSymbolAddress((void**)&Bh, g_Bh);    cudaGetSymbolAddress((void**)&Bl, g_Bl);
    cudaGetSymbolAddress((void**)&Ch, g_Ch);    cudaGetSymbolAddress((void**)&Cl, g_Cl);
    cudaGetSymbolAddress((void**)&ynh, g_ynh);  cudaGetSymbolAddress((void**)&ynl, g_ynl);

    cudaFuncSetAttribute(gemm_wmma<256>, cudaFuncAttributeMaxDynamicSharedMemorySize, SMEM_BM256);
    cudaFuncSetAttribute(gemm_wmma<128>, cudaFuncAttributeMaxDynamicSharedMemorySize, SMEM_BM128);

    // 0) split fp32 -> bf16 hi/lo for GEMM operands
    split_kernel<<<(T_LEN * HID + 255) / 256, 256>>>(hs, hsh, hsl, T_LEN * HID);
    split_kernel<<<(PROJ * HID + 255) / 256, 256>>>(w1, w1h, w1l, PROJ * HID);
    split_kernel<<<(HID * INTER + 255) / 256, 256>>>(w2, w2h, w2l, HID * INTER);

    // 1) in_proj: zx[T, PROJ] = hs @ w1^T  (b1 fused into consumers) — BM=256, one wave
    gemm_wmma<256><<<dim3(PROJ / 128, T_LEN / 256), 256, SMEM_BM256>>>(
        hsh, hsl, w1h, w1l, zx, T_LEN, PROJ, HID);

    // 2) conv + silu + split
    conv_silu_kernel<<<(T_LEN * CONV_DIM + 255) / 256, 256>>>(cw, b1);

    // 3) dt / g / Ls
    prep_kernel<<<T_LEN, 128>>>(dtb, alog, lpar, b1);

    // 4) cumsum of g per head
    scan_kernel<<<H_HEADS, 1024>>>();

    // 5) scores[t,s] = C[t]·B[s]  — BM=128
    gemm_wmma<128><<<dim3(T_LEN / 128, T_LEN / 128), 128, SMEM_BM128>>>(
        Ch, Cl, Bh, Bl, scores, T_LEN, T_LEN, N_STATE);

    // 6) attention
    attn_kernel<<<dim3(T_LEN / 64, H_HEADS), 256>>>(lvl, Dp);

    // 7) gated RMSNorm (emits bf16 hi/lo)
    gated_norm_kernel<<<T_LEN, 256>>>(rmsw, b1);

    // 8) out_proj: out = yn @ w2^T + b2 — BM=128
    gemm_wmma<128><<<dim3(HID / 128, T_LEN / 128), 128, SMEM_BM128>>>(
        ynh, ynl, w2h, w2l, out, T_LEN, HID, INTER);
    bias_add_kernel<<<(T_LEN * HID + 255) / 256, 256>>>(out, b2, HID, T_LEN * HID);
}

// round 10
// speedup vs baseline: 1.1244x; 1.1244x over previous
#include <cuda_runtime.h>
#include <cuda_bf16.h>
#include <mma.h>
#include <cstdint>
#include <cstdio>

using namespace nvcuda;

// ---------------- Problem constants ----------------
#define T_LEN   1024
#define HID     1024
#define H_HEADS 32
#define P_DIM   64
#define N_STATE 128
#define NL      15
#define KCONV   4
#define INTER   2048          // H*P
#define CONV_DIM 2304         // INTER + 2*N
#define PROJ    4864          // INTER + CONV_DIM + H*(NL+1)
#define DT_OFF  4352          // INTER + CONV_DIM
#define EPSNRM  1e-5f

// ---------------- Scratch (device globals; no allocation allowed) ----------------
__device__ float g_zx[T_LEN * PROJ];        // in_proj output (bias fused in consumers)
__device__ float g_x[T_LEN * INTER];        // conv+silu x part (unscaled)
__device__ float g_dt[T_LEN * H_HEADS];     // softplus dt, [t][h]
__device__ float g_g[H_HEADS * T_LEN];      // per-step log decay, [h][t]
__device__ float g_cg[H_HEADS * T_LEN];     // cumsum, [h][t]
__device__ float g_Ls[T_LEN * H_HEADS * NL];// level scales [t][h][l]
__device__ float g_scores[T_LEN * T_LEN];   // C·B^T (head-independent, G=1)
__device__ float g_y[T_LEN * INTER];        // attention output + D residual

// bf16 hi/lo split operands for tensor-core GEMMs
__device__ __nv_bfloat16 g_hsh[T_LEN * HID],  g_hsl[T_LEN * HID];
__device__ __nv_bfloat16 g_w1h[PROJ * HID],   g_w1l[PROJ * HID];
__device__ __nv_bfloat16 g_w2h[HID * INTER],  g_w2l[HID * INTER];
__device__ __nv_bfloat16 g_Bh[T_LEN * N_STATE], g_Bl[T_LEN * N_STATE];
__device__ __nv_bfloat16 g_Ch[T_LEN * N_STATE], g_Cl[T_LEN * N_STATE];
__device__ __nv_bfloat16 g_ynh[T_LEN * INTER],  g_ynl[T_LEN * INTER];

__device__ __forceinline__ float softplus_f(float x) {
    return (x > 20.f) ? x : log1pf(expf(x));
}
__device__ __forceinline__ float silu_f(float x) {
    return x / (1.f + expf(-x));
}
__device__ __forceinline__ void split_bf16(float x, __nv_bfloat16& h, __nv_bfloat16& l) {
    h = __float2bfloat16(x);
    l = __float2bfloat16(x - __bfloat162float(h));
}

#define CP_ASYNC16(smem_u32, gptr) \
    asm volatile("cp.async.cg.shared.global [%0], [%1], 16;\n" :: "r"(smem_u32), "l"(gptr))
#define CP_COMMIT() asm volatile("cp.async.commit_group;\n" ::: "memory")
#define CP_WAIT(n)  asm volatile("cp.async.wait_group %0;\n" :: "n"(n) : "memory")

// ---------------- fp32 -> bf16 hi/lo split ----------------
__global__ void split_kernel(const float* __restrict__ src,
                             __nv_bfloat16* __restrict__ hi,
                             __nv_bfloat16* __restrict__ lo, int n) {
    int i = blockIdx.x * blockDim.x + threadIdx.x;
    if (i < n) {
        __nv_bfloat16 h, l;
        split_bf16(src[i], h, l);
        hi[i] = h; lo[i] = l;
    }
}

// ---------------- bias add (final output epilogue) ----------------
__global__ void bias_add_kernel(float* __restrict__ C, const float* __restrict__ bias,
                                int N, int total) {
    int i = blockIdx.x * blockDim.x + threadIdx.x;
    if (i < total) C[i] += bias[i % N];
}

// ---------------- Tensor-core NT GEMM, split-bf16 x3, pass-reordered MMA schedule ------
// C[m,n] = sum_k A[m,k]*B[n,k], A=Ah+Al, B=Bh+Bl; C ~= Ah*Bh + Al*Bh + Ah*Bl.
// Block tile 128 x BN, K-tile 32, 8 warps (4m x 2n), warp tile 32 x BN/2.
// Inner loop sweeps ALL accumulators once per pass so back-to-back HMMAs are
// independent (same-acc reuse distance = 2*NF MMAs instead of 1).
template <int BN>
__global__ __launch_bounds__(256, 2)
void gemm_bf16x3_nt(const __nv_bfloat16* __restrict__ Ah, const __nv_bfloat16* __restrict__ Al,
                    const __nv_bfloat16* __restrict__ Bh, const __nv_bfloat16* __restrict__ Bl,
                    float* __restrict__ C, int M, int N, int K) {
    constexpr int NF = BN / 32;                    // 16-wide b frags per warp
    __shared__ __nv_bfloat16 sA[2][2][128][40];    // [buf][hi/lo][row][k]
    __shared__ __nv_bfloat16 sB[2][2][BN][40];
    const int tid = threadIdx.x;
    const int bm = blockIdx.y * 128, bn = blockIdx.x * BN;
    const int warp = tid >> 5;
    const int wm = (warp & 3) * 32;
    const int wn = (warp >> 2) * (BN / 2);

    wmma::fragment<wmma::accumulator, 16, 16, 16, float> acc[2][NF];
#pragma unroll
    for (int i = 0; i < 2; i++)
#pragma unroll
        for (int j = 0; j < NF; j++) wmma::fill_fragment(acc[i][j], 0.f);

    const int lr = tid >> 2;        // 0..63
    const int lc = (tid & 3) * 8;   // 0,8,16,24 bf16 (16B chunks)

    auto load_stage = [&](int k0, int buf) {
#pragma unroll
        for (int r = 0; r < 128; r += 64) {
            const size_t aoff = (size_t)(bm + lr + r) * K + k0 + lc;
            CP_ASYNC16((unsigned)__cvta_generic_to_shared(&sA[buf][0][lr + r][lc]), Ah + aoff);
            CP_ASYNC16((unsigned)__cvta_generic_to_shared(&sA[buf][1][lr + r][lc]), Al + aoff);
        }
#pragma unroll
        for (int r = 0; r < BN; r += 64) {
            const size_t boff = (size_t)(bn + lr + r) * K + k0 + lc;
            CP_ASYNC16((unsigned)__cvta_generic_to_shared(&sB[buf][0][lr + r][lc]), Bh + boff);
            CP_ASYNC16((unsigned)__cvta_generic_to_shared(&sB[buf][1][lr + r][lc]), Bl + boff);
        }
    };

    load_stage(0, 0);
    CP_COMMIT();

    const int nt = K >> 5;
    for (int kt = 0; kt < nt; kt++) {
        const int buf = kt & 1;
        if (kt + 1 < nt) {
            load_stage((kt + 1) << 5, buf ^ 1);
            CP_COMMIT();
            CP_WAIT(1);
        } else {
            CP_WAIT(0);
        }
        __syncthreads();
#pragma unroll
        for (int ks = 0; ks < 32; ks += 16) {
            wmma::fragment<wmma::matrix_a, 16, 16, 16, __nv_bfloat16, wmma::row_major> ah[2], al[2];
#pragma unroll
            for (int i = 0; i < 2; i++) {
                wmma::load_matrix_sync(ah[i], &sA[buf][0][wm + 16 * i][ks], 40);
                wmma::load_matrix_sync(al[i], &sA[buf][1][wm + 16 * i][ks], 40);
            }
            // pass 1: Ah * Bh — all accs, back-to-back MMAs independent
#pragma unroll
            for (int j = 0; j < NF; j++) {
                wmma::fragment<wmma::matrix_b, 16, 16, 16, __nv_bfloat16, wmma::col_major> bf;
                wmma::load_matrix_sync(bf, &sB[buf][0][wn + 16 * j][ks], 40);
                wmma::mma_sync(acc[0][j], ah[0], bf, acc[0][j]);
                wmma::mma_sync(acc[1][j], ah[1], bf, acc[1][j]);
            }
            // pass 2: Al * Bh
#pragma unroll
            for (int j = 0; j < NF; j++) {
                wmma::fragment<wmma::matrix_b, 16, 16, 16, __nv_bfloat16, wmma::col_major> bf;
                wmma::load_matrix_sync(bf, &sB[buf][0][wn + 16 * j][ks], 40);
                wmma::mma_sync(acc[0][j], al[0], bf, acc[0][j]);
                wmma::mma_sync(acc[1][j], al[1], bf, acc[1][j]);
            }
            // pass 3: Ah * Bl
#pragma unroll
            for (int j = 0; j < NF; j++) {
                wmma::fragment<wmma::matrix_b, 16, 16, 16, __nv_bfloat16, wmma::col_major> bf;
                wmma::load_matrix_sync(bf, &sB[buf][1][wn + 16 * j][ks], 40);
                wmma::mma_sync(acc[0][j], ah[0], bf, acc[0][j]);
                wmma::mma_sync(acc[1][j], ah[1], bf, acc[1][j]);
            }
        }
        __syncthreads();
    }
#pragma unroll
    for (int i = 0; i < 2; i++)
#pragma unroll
        for (int j = 0; j < NF; j++)
            wmma::store_matrix_sync(C + (size_t)(bm + wm + 16 * i) * N + bn + wn + 16 * j,
                                    acc[i][j], N, wmma::mem_row_major);
}

// ---------------- Depthwise causal conv (K=4) + SiLU + split (b1 fused) ----------------
__global__ void conv_silu_kernel(const float* __restrict__ conv_w,
                                 const float* __restrict__ b1) {
    int idx = blockIdx.x * blockDim.x + threadIdx.x;
    if (idx >= T_LEN * CONV_DIM) return;
    int t = idx / CONV_DIM;
    int c = idx % CONV_DIM;
    const float bias = b1[INTER + c];
    float acc = 0.f;
#pragma unroll
    for (int w = 0; w < KCONV; w++) {
        int ts = t - (KCONV - 1) + w;
        if (ts >= 0)
            acc = fmaf(g_zx[(size_t)ts * PROJ + INTER + c] + bias, conv_w[c * KCONV + w], acc);
    }
    float s = silu_f(acc);
    if (c < INTER) {
        g_x[(size_t)t * INTER + c] = s;
    } else if (c < INTER + N_STATE) {
        __nv_bfloat16 h, l; split_bf16(s, h, l);
        int o = t * N_STATE + (c - INTER);
        g_Bh[o] = h; g_Bl[o] = l;
    } else {
        __nv_bfloat16 h, l; split_bf16(s, h, l);
        int o = t * N_STATE + (c - INTER - N_STATE);
        g_Ch[o] = h; g_Cl[o] = l;
    }
}

// ---------------- dt / g / Ls prep (b1 fused) ----------------
__global__ void prep_kernel(const float* __restrict__ dt_bias,
                            const float* __restrict__ A_log,
                            const float* __restrict__ L_param,
                            const float* __restrict__ b1) {
    int t = blockIdx.x;
    const float* row = g_zx + (size_t)t * PROJ + DT_OFF;
    const float* brow = b1 + DT_OFF;
    for (int i = threadIdx.x; i < H_HEADS; i += blockDim.x) {
        float d = softplus_f(row[i] + brow[i] + dt_bias[i]);
        g_dt[t * H_HEADS + i] = d;
        g_g[i * T_LEN + t] = -expf(A_log[i]) * d;
    }
    for (int i = threadIdx.x; i < H_HEADS * NL; i += blockDim.x) {
        g_Ls[(size_t)t * (H_HEADS * NL) + i] =
            softplus_f(L_param[i] * (row[H_HEADS + i] + brow[H_HEADS + i]));
    }
}

// ---------------- inclusive scan of g over t, per head ----------------
__global__ __launch_bounds__(1024)
void scan_kernel() {
    __shared__ float sh[T_LEN];
    int h = blockIdx.x;
    int t = threadIdx.x;
    sh[t] = g_g[h * T_LEN + t];
    __syncthreads();
    for (int off = 1; off < T_LEN; off <<= 1) {
        float add = (t >= off) ? sh[t - off] : 0.f;
        __syncthreads();
        sh[t] += add;
        __syncthreads();
    }
    g_cg[h * T_LEN + t] = sh[t];
}

// ---------------- Attention: per (head, t-tile of 64) ----------------
__global__ __launch_bounds__(256)
void attn_kernel(const int* __restrict__ lvl, const float* __restrict__ Dp) {
    const int h = blockIdx.y;
    const int t0 = blockIdx.x * 64;
    __shared__ float s_w[64][65];
    __shared__ float s_v[64][65];
    __shared__ float s_cgt[64];
    __shared__ float s_cgs[64];
    __shared__ float s_Lst[64][16];
    const int tid = threadIdx.x;

    if (tid < 64) s_cgt[tid] = g_cg[h * T_LEN + t0 + tid];
    for (int i = tid; i < 64 * NL; i += 256) {
        int r = i / NL, l = i % NL;
        s_Lst[r][l] = g_Ls[((size_t)(t0 + r) * H_HEADS + h) * NL + l];
    }

    float acc[4][4];
#pragma unroll
    for (int i = 0; i < 4; i++)
#pragma unroll
        for (int j = 0; j < 4; j++) acc[i][j] = 0.f;

    const int tr = (tid >> 4) << 2;
    const int tc = (tid & 15) << 2;

    for (int s0 = 0; s0 <= t0; s0 += 64) {
        __syncthreads();
        if (s0 < t0) {
            float maxld = g_cg[h * T_LEN + t0] - g_cg[h * T_LEN + s0 + 63];
            if (maxld < -30.f) continue;
        }
        for (int i = tid; i < 64 * 64; i += 256) {
            int r = i >> 6, c = i & 63;
            s_w[r][c] = g_scores[(size_t)(t0 + r) * T_LEN + s0 + c];
        }
        for (int i = tid; i < 64 * 64; i += 256) {
            int r = i >> 6, p = i & 63;
            s_v[r][p] = g_x[(size_t)(s0 + r) * INTER + h * P_DIM + p] *
                        g_dt[(s0 + r) * H_HEADS + h];
        }
        if (tid < 64) s_cgs[tid] = g_cg[h * T_LEN + s0 + tid];
        __syncthreads();
        for (int i = tid; i < 64 * 64; i += 256) {
            int r = i >> 6, c = i & 63;
            int tg = t0 + r, sg = s0 + c;
            float w = 0.f;
            if (sg <= tg) {
                int L = lvl[(size_t)tg * T_LEN + sg];
                w = s_w[r][c] * __expf(s_cgt[r] - s_cgs[c]) * s_Lst[r][L];
            }
            s_w[r][c] = w;
        }
        __syncthreads();
#pragma unroll 8
        for (int k = 0; k < 64; k++) {
            float a[4], b[4];
#pragma unroll
            for (int i = 0; i < 4; i++) a[i] = s_w[tr + i][k];
#pragma unroll
            for (int j = 0; j < 4; j++) b[j] = s_v[k][tc + j];
#pragma unroll
            for (int i = 0; i < 4; i++)
#pragma unroll
                for (int j = 0; j < 4; j++)
                    acc[i][j] = fmaf(a[i], b[j], acc[i][j]);
        }
    }
    const float Dh = Dp[h];
#pragma unroll
    for (int i = 0; i < 4; i++) {
        int tg = t0 + tr + i;
#pragma unroll
        for (int j = 0; j < 4; j++) {
            int col = h * P_DIM + tc + j;
            g_y[(size_t)tg * INTER + col] =
                acc[i][j] + g_x[(size_t)tg * INTER + col] * Dh;
        }
    }
}

// ---------------- gated RMSNorm (b1 fused into z), bf16 hi/lo out ----------------
__global__ __launch_bounds__(256)
void gated_norm_kernel(const float* __restrict__ rmsw, const float* __restrict__ b1) {
    const int t = blockIdx.x;
    __shared__ float red[8];
    float vals[8];
    float local = 0.f;
#pragma unroll
    for (int i = 0; i < 8; i++) {
        int c = threadIdx.x + i * 256;
        float z = g_zx[(size_t)t * PROJ + c] + b1[c];
        float yv = g_y[(size_t)t * INTER + c];
        float gv = yv * silu_f(z);
        vals[i] = gv;
        local = fmaf(gv, gv, local);
    }
#pragma unroll
    for (int off = 16; off > 0; off >>= 1)
        local += __shfl_xor_sync(0xffffffffu, local, off);
    if ((threadIdx.x & 31) == 0) red[threadIdx.x >> 5] = local;
    __syncthreads();
    if (threadIdx.x < 8) {
        float v = red[threadIdx.x];
#pragma unroll
        for (int off = 4; off > 0; off >>= 1)
            v += __shfl_xor_sync(0xffu, v, off);
        if (threadIdx.x == 0) red[0] = v;
    }
    __syncthreads();
    const float inv = rsqrtf(red[0] / (float)INTER + EPSNRM);
#pragma unroll
    for (int i = 0; i < 8; i++) {
        int c = threadIdx.x + i * 256;
        float v = vals[i] * inv * rmsw[c];
        __nv_bfloat16 h, l; split_bf16(v, h, l);
        g_ynh[(size_t)t * INTER + c] = h;
        g_ynl[(size_t)t * INTER + c] = l;
    }
}

// ---------------- Launch ----------------
extern "C" void kernel_launch(void* const* d_in, const int* in_sizes, int n_in,
                              void* d_out, int out_size) {
    const float* hs    = (const float*)d_in[0];
    const float* w1    = (const float*)d_in[1];
    const float* b1    = (const float*)d_in[2];
    const float* cw    = (const float*)d_in[3];
    const float* dtb   = (const float*)d_in[4];
    const float* alog  = (const float*)d_in[5];
    const float* lpar  = (const float*)d_in[6];
    const float* Dp    = (const float*)d_in[7];
    const float* rmsw  = (const float*)d_in[8];
    const float* w2    = (const float*)d_in[9];
    const float* b2    = (const float*)d_in[10];
    const int*   lvl   = (const int*)d_in[11];
    float* out = (float*)d_out;

    float *zx, *scores;
    __nv_bfloat16 *hsh, *hsl, *w1h, *w1l, *w2h, *w2l, *Bh, *Bl, *Ch, *Cl, *ynh, *ynl;
    cudaGetSymbolAddress((void**)&zx, g_zx);
    cudaGetSymbolAddress((void**)&scores, g_scores);
    cudaGetSymbolAddress((void**)&hsh, g_hsh);  cudaGetSymbolAddress((void**)&hsl, g_hsl);
    cudaGetSymbolAddress((void**)&w1h, g_w1h);  cudaGetSymbolAddress((void**)&w1l, g_w1l);
    cudaGetSymbolAddress((void**)&w2h, g_w2h);  cudaGetSymbolAddress((void**)&w2l, g_w2l);
    cudaGetSymbolAddress((void**)&Bh, g_Bh);    cudaGetSymbolAddress((void**)&Bl, g_Bl);
    cudaGetSymbolAddress((void**)&Ch, g_Ch);    cudaGetSymbolAddress((void**)&Cl, g_Cl);
    cudaGetSymbolAddress((void**)&ynh, g_ynh);  cudaGetSymbolAddress((void**)&ynl, g_ynl);

    // 0) split fp32 -> bf16 hi/lo for GEMM operands
    split_kernel<<<(T_LEN * HID + 255) / 256, 256>>>(hs, hsh, hsl, T_LEN * HID);
    split_kernel<<<(PROJ * HID + 255) / 256, 256>>>(w1, w1h, w1l, PROJ * HID);
    split_kernel<<<(HID * INTER + 255) / 256, 256>>>(w2, w2h, w2l, HID * INTER);

    // 1) in_proj: zx[T, PROJ] = hs @ w1^T  (b1 fused into consumers)
    gemm_bf16x3_nt<128><<<dim3(PROJ / 128, T_LEN / 128), 256>>>(hsh, hsl, w1h, w1l, zx,
                                                                T_LEN, PROJ, HID);

    // 2) conv + silu + split
    conv_silu_kernel<<<(T_LEN * CONV_DIM + 255) / 256, 256>>>(cw, b1);

    // 3) dt / g / Ls
    prep_kernel<<<T_LEN, 128>>>(dtb, alog, lpar, b1);

    // 4) cumsum of g per head
    scan_kernel<<<H_HEADS, 1024>>>();

    // 5) scores[t,s] = C[t]·B[s]  — BN=64 for full-chip grid
    gemm_bf16x3_nt<64><<<dim3(T_LEN / 64, T_LEN / 128), 256>>>(Ch, Cl, Bh, Bl, scores,
                                                               T_LEN, T_LEN, N_STATE);

    // 6) attention
    attn_kernel<<<dim3(T_LEN / 64, H_HEADS), 256>>>(lvl, Dp);

    // 7) gated RMSNorm (emits bf16 hi/lo)
    gated_norm_kernel<<<T_LEN, 256>>>(rmsw, b1);

    // 8) out_proj: out = yn @ w2^T + b2 — BN=64 for full-chip grid
    gemm_bf16x3_nt<64><<<dim3(HID / 64, T_LEN / 128), 256>>>(ynh, ynl, w2h, w2l, out,
                                                             T_LEN, HID, INTER);
    bias_add_kernel<<<(T_LEN * HID + 255) / 256, 256>>>(out, b2, HID, T_LEN * HID);
}

// round 11
// speedup vs baseline: 1.4614x; 1.2997x over previous
#include <cuda_runtime.h>
#include <cuda_bf16.h>
#include <cuda_fp16.h>
#include <mma.h>
#include <cstdint>
#include <cstdio>

using namespace nvcuda;

// ---------------- Problem constants ----------------
#define T_LEN   1024
#define HID     1024
#define H_HEADS 32
#define P_DIM   64
#define N_STATE 128
#define NL      15
#define KCONV   4
#define INTER   2048          // H*P
#define CONV_DIM 2304         // INTER + 2*N
#define PROJ    4864          // INTER + CONV_DIM + H*(NL+1)
#define DT_OFF  4352          // INTER + CONV_DIM
#define EPSNRM  1e-5f

// ---------------- Scratch (device globals; no allocation allowed) ----------------
__device__ float g_zx[T_LEN * PROJ];        // in_proj output (bias fused in consumers)
__device__ float g_x[T_LEN * INTER];        // conv+silu x part (unscaled)
__device__ float g_dt[T_LEN * H_HEADS];     // softplus dt, [t][h]
__device__ float g_g[H_HEADS * T_LEN];      // per-step log decay, [h][t]
__device__ float g_cg[H_HEADS * T_LEN];     // cumsum, [h][t]
__device__ float g_Ls[T_LEN * H_HEADS * NL];// level scales [t][h][l]
__device__ float g_scores[T_LEN * T_LEN];   // C·B^T (head-independent, G=1)
__device__ float g_y[T_LEN * INTER];        // attention output + D residual

// fp16 operands: A-side compensated (hi/lo), B-side single
__device__ __half g_hsh[T_LEN * HID],  g_hsl[T_LEN * HID];   // hs hi/lo
__device__ __half g_w1[PROJ * HID];                          // w1 single
__device__ __half g_w2[HID * INTER];                         // w2 single
__device__ __half g_Bm16[T_LEN * N_STATE];                   // keys single
__device__ __half g_Ch[T_LEN * N_STATE], g_Cl[T_LEN * N_STATE]; // queries hi/lo
__device__ __half g_ynh[T_LEN * INTER],  g_ynl[T_LEN * INTER];  // yn hi/lo

__device__ __forceinline__ float softplus_f(float x) {
    return (x > 20.f) ? x : log1pf(expf(x));
}
__device__ __forceinline__ float silu_f(float x) {
    return x / (1.f + expf(-x));
}
__device__ __forceinline__ void split_fp16(float x, __half& h, __half& l) {
    h = __float2half(x);
    l = __float2half(x - __half2float(h));
}

#define CP_ASYNC16(smem_u32, gptr) \
    asm volatile("cp.async.cg.shared.global [%0], [%1], 16;\n" :: "r"(smem_u32), "l"(gptr))
#define CP_COMMIT() asm volatile("cp.async.commit_group;\n" ::: "memory")
#define CP_WAIT(n)  asm volatile("cp.async.wait_group %0;\n" :: "n"(n) : "memory")

// ---------------- fp32 -> fp16 hi/lo split ----------------
__global__ void split_pair_kernel(const float* __restrict__ src,
                                  __half* __restrict__ hi,
                                  __half* __restrict__ lo, int n) {
    int i = blockIdx.x * blockDim.x + threadIdx.x;
    if (i < n) {
        __half h, l;
        split_fp16(src[i], h, l);
        hi[i] = h; lo[i] = l;
    }
}

// ---------------- fp32 -> fp16 single convert ----------------
__global__ void cvt_fp16_kernel(const float* __restrict__ src,
                                __half* __restrict__ dst, int n) {
    int i = blockIdx.x * blockDim.x + threadIdx.x;
    if (i < n) dst[i] = __float2half(src[i]);
}

// ---------------- bias add (final output epilogue) ----------------
__global__ void bias_add_kernel(float* __restrict__ C, const float* __restrict__ bias,
                                int N, int total) {
    int i = blockIdx.x * blockDim.x + threadIdx.x;
    if (i < total) C[i] += bias[i % N];
}

// ---------------- Tensor-core NT GEMM, fp16 A-compensated x2 ----------------
// C[m,n] = sum_k A[m,k]*B[n,k], A = Ah+Al (fp16 pair), B = fp16 single.
// C ~= Ah*B + Al*B  (error ~ A*(B - fp16(B)) ~ 2^-12 rel).
// Block tile 128 x BN, K-tile 32, 8 warps (4m x 2n), warp tile 32 x BN/2.
template <int BN>
__global__ __launch_bounds__(256, 2)
void gemm_fp16x2_nt(const __half* __restrict__ Ah, const __half* __restrict__ Al,
                    const __half* __restrict__ B,
                    float* __restrict__ C, int M, int N, int K) {
    constexpr int NF = BN / 32;                 // 16-wide b frags per warp
    __shared__ __half sA[2][2][128][40];        // [buf][hi/lo][row][k]
    __shared__ __half sB[2][BN][40];
    const int tid = threadIdx.x;
    const int bm = blockIdx.y * 128, bn = blockIdx.x * BN;
    const int warp = tid >> 5;
    const int wm = (warp & 3) * 32;
    const int wn = (warp >> 2) * (BN / 2);

    wmma::fragment<wmma::accumulator, 16, 16, 16, float> acc[2][NF];
#pragma unroll
    for (int i = 0; i < 2; i++)
#pragma unroll
        for (int j = 0; j < NF; j++) wmma::fill_fragment(acc[i][j], 0.f);

    const int lr = tid >> 2;        // 0..63
    const int lc = (tid & 3) * 8;   // 0,8,16,24 fp16 (16B chunks)

    auto load_stage = [&](int k0, int buf) {
#pragma unroll
        for (int r = 0; r < 128; r += 64) {
            const size_t aoff = (size_t)(bm + lr + r) * K + k0 + lc;
            CP_ASYNC16((unsigned)__cvta_generic_to_shared(&sA[buf][0][lr + r][lc]), Ah + aoff);
            CP_ASYNC16((unsigned)__cvta_generic_to_shared(&sA[buf][1][lr + r][lc]), Al + aoff);
        }
#pragma unroll
        for (int r = 0; r < BN; r += 64) {
            const size_t boff = (size_t)(bn + lr + r) * K + k0 + lc;
            CP_ASYNC16((unsigned)__cvta_generic_to_shared(&sB[buf][lr + r][lc]), B + boff);
        }
    };

    load_stage(0, 0);
    CP_COMMIT();

    const int nt = K >> 5;
    for (int kt = 0; kt < nt; kt++) {
        const int buf = kt & 1;
        if (kt + 1 < nt) {
            load_stage((kt + 1) << 5, buf ^ 1);
            CP_COMMIT();
            CP_WAIT(1);
        } else {
            CP_WAIT(0);
        }
        __syncthreads();
#pragma unroll
        for (int ks = 0; ks < 32; ks += 16) {
            wmma::fragment<wmma::matrix_a, 16, 16, 16, __half, wmma::row_major> ah[2], al[2];
#pragma unroll
            for (int i = 0; i < 2; i++) {
                wmma::load_matrix_sync(ah[i], &sA[buf][0][wm + 16 * i][ks], 40);
                wmma::load_matrix_sync(al[i], &sA[buf][1][wm + 16 * i][ks], 40);
            }
#pragma unroll
            for (int j = 0; j < NF; j++) {
                wmma::fragment<wmma::matrix_b, 16, 16, 16, __half, wmma::col_major> bf;
                wmma::load_matrix_sync(bf, &sB[buf][wn + 16 * j][ks], 40);
                wmma::mma_sync(acc[0][j], ah[0], bf, acc[0][j]);
                wmma::mma_sync(acc[1][j], ah[1], bf, acc[1][j]);
                wmma::mma_sync(acc[0][j], al[0], bf, acc[0][j]);
                wmma::mma_sync(acc[1][j], al[1], bf, acc[1][j]);
            }
        }
        __syncthreads();
    }
#pragma unroll
    for (int i = 0; i < 2; i++)
#pragma unroll
        for (int j = 0; j < NF; j++)
            wmma::store_matrix_sync(C + (size_t)(bm + wm + 16 * i) * N + bn + wn + 16 * j,
                                    acc[i][j], N, wmma::mem_row_major);
}

// ---------------- Depthwise causal conv (K=4) + SiLU + split (b1 fused) ----------------
__global__ void conv_silu_kernel(const float* __restrict__ conv_w,
                                 const float* __restrict__ b1) {
    int idx = blockIdx.x * blockDim.x + threadIdx.x;
    if (idx >= T_LEN * CONV_DIM) return;
    int t = idx / CONV_DIM;
    int c = idx % CONV_DIM;
    const float bias = b1[INTER + c];
    float acc = 0.f;
#pragma unroll
    for (int w = 0; w < KCONV; w++) {
        int ts = t - (KCONV - 1) + w;
        if (ts >= 0)
            acc = fmaf(g_zx[(size_t)ts * PROJ + INTER + c] + bias, conv_w[c * KCONV + w], acc);
    }
    float s = silu_f(acc);
    if (c < INTER) {
        g_x[(size_t)t * INTER + c] = s;
    } else if (c < INTER + N_STATE) {
        g_Bm16[t * N_STATE + (c - INTER)] = __float2half(s);   // keys: B-side single
    } else {
        __half h, l; split_fp16(s, h, l);                      // queries: A-side pair
        int o = t * N_STATE + (c - INTER - N_STATE);
        g_Ch[o] = h; g_Cl[o] = l;
    }
}

// ---------------- dt / g / Ls prep (b1 fused) ----------------
__global__ void prep_kernel(const float* __restrict__ dt_bias,
                            const float* __restrict__ A_log,
                            const float* __restrict__ L_param,
                            const float* __restrict__ b1) {
    int t = blockIdx.x;
    const float* row = g_zx + (size_t)t * PROJ + DT_OFF;
    const float* brow = b1 + DT_OFF;
    for (int i = threadIdx.x; i < H_HEADS; i += blockDim.x) {
        float d = softplus_f(row[i] + brow[i] + dt_bias[i]);
        g_dt[t * H_HEADS + i] = d;
        g_g[i * T_LEN + t] = -expf(A_log[i]) * d;
    }
    for (int i = threadIdx.x; i < H_HEADS * NL; i += blockDim.x) {
        g_Ls[(size_t)t * (H_HEADS * NL) + i] =
            softplus_f(L_param[i] * (row[H_HEADS + i] + brow[H_HEADS + i]));
    }
}

// ---------------- inclusive scan of g over t, per head ----------------
__global__ __launch_bounds__(1024)
void scan_kernel() {
    __shared__ float sh[T_LEN];
    int h = blockIdx.x;
    int t = threadIdx.x;
    sh[t] = g_g[h * T_LEN + t];
    __syncthreads();
    for (int off = 1; off < T_LEN; off <<= 1) {
        float add = (t >= off) ? sh[t - off] : 0.f;
        __syncthreads();
        sh[t] += add;
        __syncthreads();
    }
    g_cg[h * T_LEN + t] = sh[t];
}

// ---------------- Attention: per (head, t-tile of 64) ----------------
__global__ __launch_bounds__(256)
void attn_kernel(const int* __restrict__ lvl, const float* __restrict__ Dp) {
    const int h = blockIdx.y;
    const int t0 = blockIdx.x * 64;
    __shared__ float s_w[64][65];
    __shared__ float s_v[64][65];
    __shared__ float s_cgt[64];
    __shared__ float s_cgs[64];
    __shared__ float s_Lst[64][16];
    const int tid = threadIdx.x;

    if (tid < 64) s_cgt[tid] = g_cg[h * T_LEN + t0 + tid];
    for (int i = tid; i < 64 * NL; i += 256) {
        int r = i / NL, l = i % NL;
        s_Lst[r][l] = g_Ls[((size_t)(t0 + r) * H_HEADS + h) * NL + l];
    }

    float acc[4][4];
#pragma unroll
    for (int i = 0; i < 4; i++)
#pragma unroll
        for (int j = 0; j < 4; j++) acc[i][j] = 0.f;

    const int tr = (tid >> 4) << 2;
    const int tc = (tid & 15) << 2;

    for (int s0 = 0; s0 <= t0; s0 += 64) {
        __syncthreads();
        if (s0 < t0) {
            float maxld = g_cg[h * T_LEN + t0] - g_cg[h * T_LEN + s0 + 63];
            if (maxld < -30.f) continue;
        }
        for (int i = tid; i < 64 * 64; i += 256) {
            int r = i >> 6, c = i & 63;
            s_w[r][c] = g_scores[(size_t)(t0 + r) * T_LEN + s0 + c];
        }
        for (int i = tid; i < 64 * 64; i += 256) {
            int r = i >> 6, p = i & 63;
            s_v[r][p] = g_x[(size_t)(s0 + r) * INTER + h * P_DIM + p] *
                        g_dt[(s0 + r) * H_HEADS + h];
        }
        if (tid < 64) s_cgs[tid] = g_cg[h * T_LEN + s0 + tid];
        __syncthreads();
        for (int i = tid; i < 64 * 64; i += 256) {
            int r = i >> 6, c = i & 63;
            int tg = t0 + r, sg = s0 + c;
            float w = 0.f;
            if (sg <= tg) {
                int L = lvl[(size_t)tg * T_LEN + sg];
                w = s_w[r][c] * __expf(s_cgt[r] - s_cgs[c]) * s_Lst[r][L];
            }
            s_w[r][c] = w;
        }
        __syncthreads();
#pragma unroll 8
        for (int k = 0; k < 64; k++) {
            float a[4], b[4];
#pragma unroll
            for (int i = 0; i < 4; i++) a[i] = s_w[tr + i][k];
#pragma unroll
            for (int j = 0; j < 4; j++) b[j] = s_v[k][tc + j];
#pragma unroll
            for (int i = 0; i < 4; i++)
#pragma unroll
                for (int j = 0; j < 4; j++)
                    acc[i][j] = fmaf(a[i], b[j], acc[i][j]);
        }
    }
    const float Dh = Dp[h];
#pragma unroll
    for (int i = 0; i < 4; i++) {
        int tg = t0 + tr + i;
#pragma unroll
        for (int j = 0; j < 4; j++) {
            int col = h * P_DIM + tc + j;
            g_y[(size_t)tg * INTER + col] =
                acc[i][j] + g_x[(size_t)tg * INTER + col] * Dh;
        }
    }
}

// ---------------- gated RMSNorm (b1 fused into z), fp16 hi/lo out ----------------
__global__ __launch_bounds__(256)
void gated_norm_kernel(const float* __restrict__ rmsw, const float* __restrict__ b1) {
    const int t = blockIdx.x;
    __shared__ float red[8];
    float vals[8];
    float local = 0.f;
#pragma unroll
    for (int i = 0; i < 8; i++) {
        int c = threadIdx.x + i * 256;
        float z = g_zx[(size_t)t * PROJ + c] + b1[c];
        float yv = g_y[(size_t)t * INTER + c];
        float gv = yv * silu_f(z);
        vals[i] = gv;
        local = fmaf(gv, gv, local);
    }
#pragma unroll
    for (int off = 16; off > 0; off >>= 1)
        local += __shfl_xor_sync(0xffffffffu, local, off);
    if ((threadIdx.x & 31) == 0) red[threadIdx.x >> 5] = local;
    __syncthreads();
    if (threadIdx.x < 8) {
        float v = red[threadIdx.x];
#pragma unroll
        for (int off = 4; off > 0; off >>= 1)
            v += __shfl_xor_sync(0xffu, v, off);
        if (threadIdx.x == 0) red[0] = v;
    }
    __syncthreads();
    const float inv = rsqrtf(red[0] / (float)INTER + EPSNRM);
#pragma unroll
    for (int i = 0; i < 8; i++) {
        int c = threadIdx.x + i * 256;
        float v = vals[i] * inv * rmsw[c];
        __half h, l; split_fp16(v, h, l);
        g_ynh[(size_t)t * INTER + c] = h;
        g_ynl[(size_t)t * INTER + c] = l;
    }
}

// ---------------- Launch ----------------
extern "C" void kernel_launch(void* const* d_in, const int* in_sizes, int n_in,
                              void* d_out, int out_size) {
    const float* hs    = (const float*)d_in[0];
    const float* w1    = (const float*)d_in[1];
    const float* b1    = (const float*)d_in[2];
    const float* cw    = (const float*)d_in[3];
    const float* dtb   = (const float*)d_in[4];
    const float* alog  = (const float*)d_in[5];
    const float* lpar  = (const float*)d_in[6];
    const float* Dp    = (const float*)d_in[7];
    const float* rmsw  = (const float*)d_in[8];
    const float* w2    = (const float*)d_in[9];
    const float* b2    = (const float*)d_in[10];
    const int*   lvl   = (const int*)d_in[11];
    float* out = (float*)d_out;

    float *zx, *scores;
    __half *hsh, *hsl, *w1p, *w2p, *Bm16, *Ch, *Cl, *ynh, *ynl;
    cudaGetSymbolAddress((void**)&zx, g_zx);
    cudaGetSymbolAddress((void**)&scores, g_scores);
    cudaGetSymbolAddress((void**)&hsh, g_hsh);  cudaGetSymbolAddress((void**)&hsl, g_hsl);
    cudaGetSymbolAddress((void**)&w1p, g_w1);   cudaGetSymbolAddress((void**)&w2p, g_w2);
    cudaGetSymbolAddress((void**)&Bm16, g_Bm16);
    cudaGetSymbolAddress((void**)&Ch, g_Ch);    cudaGetSymbolAddress((void**)&Cl, g_Cl);
    cudaGetSymbolAddress((void**)&ynh, g_ynh);  cudaGetSymbolAddress((void**)&ynl, g_ynl);

    // 0) operand conversion: A-side hi/lo pairs, B-side single fp16
    split_pair_kernel<<<(T_LEN * HID + 255) / 256, 256>>>(hs, hsh, hsl, T_LEN * HID);
    cvt_fp16_kernel<<<(PROJ * HID + 255) / 256, 256>>>(w1, w1p, PROJ * HID);
    cvt_fp16_kernel<<<(HID * INTER + 255) / 256, 256>>>(w2, w2p, HID * INTER);

    // 1) in_proj: zx[T, PROJ] = hs @ w1^T  (b1 fused into consumers)
    gemm_fp16x2_nt<128><<<dim3(PROJ / 128, T_LEN / 128), 256>>>(hsh, hsl, w1p, zx,
                                                                T_LEN, PROJ, HID);

    // 2) conv + silu + split
    conv_silu_kernel<<<(T_LEN * CONV_DIM + 255) / 256, 256>>>(cw, b1);

    // 3) dt / g / Ls
    prep_kernel<<<T_LEN, 128>>>(dtb, alog, lpar, b1);

    // 4) cumsum of g per head
    scan_kernel<<<H_HEADS, 1024>>>();

    // 5) scores[t,s] = C[t]·B[s]  — BN=64 for full-chip grid
    gemm_fp16x2_nt<64><<<dim3(T_LEN / 64, T_LEN / 128), 256>>>(Ch, Cl, Bm16, scores,
                                                               T_LEN, T_LEN, N_STATE);

    // 6) attention
    attn_kernel<<<dim3(T_LEN / 64, H_HEADS), 256>>>(lvl, Dp);

    // 7) gated RMSNorm (emits fp16 hi/lo)
    gated_norm_kernel<<<T_LEN, 256>>>(rmsw, b1);

    // 8) out_proj: out = yn @ w2^T + b2 — BN=64 for full-chip grid
    gemm_fp16x2_nt<64><<<dim3(HID / 64, T_LEN / 128), 256>>>(ynh, ynl, w2p, out,
                                                             T_LEN, HID, INTER);
    bias_add_kernel<<<(T_LEN * HID + 255) / 256, 256>>>(out, b2, HID, T_LEN * HID);
}

// round 12
// speedup vs baseline: 1.5725x; 1.0761x over previous
#include <cuda_runtime.h>
#include <cuda_bf16.h>
#include <cuda_fp16.h>
#include <mma.h>
#include <cstdint>
#include <cstdio>

using namespace nvcuda;

// ---------------- Problem constants ----------------
#define T_LEN   1024
#define HID     1024
#define H_HEADS 32
#define P_DIM   64
#define N_STATE 128
#define NL      15
#define KCONV   4
#define INTER   2048          // H*P
#define CONV_DIM 2304         // INTER + 2*N
#define PROJ    4864          // INTER + CONV_DIM + H*(NL+1)
#define DT_OFF  4352          // INTER + CONV_DIM
#define EPSNRM  1e-5f

// ---------------- Scratch (device globals; no allocation allowed) ----------------
__device__ float g_zx[T_LEN * PROJ];        // in_proj output (bias fused in consumers)
__device__ float g_x[T_LEN * INTER];        // conv+silu x part (unscaled)
__device__ float g_dt[T_LEN * H_HEADS];     // softplus dt, [t][h]
__device__ float g_g[H_HEADS * T_LEN];      // per-step log decay, [h][t]
__device__ float g_cg[H_HEADS * T_LEN];     // cumsum, [h][t]
__device__ float g_Ls[T_LEN * H_HEADS * NL];// level scales [t][h][l]
__device__ float g_scores[T_LEN * T_LEN];   // C·B^T (head-independent, G=1)
__device__ float g_y[T_LEN * INTER];        // attention output (D residual fused later)

// fp16 operands: A-side compensated (hi/lo), B-side single
__device__ __half g_hsh[T_LEN * HID],  g_hsl[T_LEN * HID];   // hs hi/lo
__device__ __half g_w1[PROJ * HID];                          // w1 single
__device__ __half g_w2[HID * INTER];                         // w2 single
__device__ __half g_Bm16[T_LEN * N_STATE];                   // keys single
__device__ __half g_Ch[T_LEN * N_STATE], g_Cl[T_LEN * N_STATE]; // queries hi/lo
__device__ __half g_ynh[T_LEN * INTER],  g_ynl[T_LEN * INTER];  // yn hi/lo

__device__ __forceinline__ float softplus_f(float x) {
    return (x > 20.f) ? x : log1pf(expf(x));
}
__device__ __forceinline__ float silu_f(float x) {
    return x / (1.f + expf(-x));
}
__device__ __forceinline__ void split_fp16(float x, __half& h, __half& l) {
    h = __float2half(x);
    l = __float2half(x - __half2float(h));
}

#define CP_ASYNC16(smem_u32, gptr) \
    asm volatile("cp.async.cg.shared.global [%0], [%1], 16;\n" :: "r"(smem_u32), "l"(gptr))
#define CP_COMMIT() asm volatile("cp.async.commit_group;\n" ::: "memory")
#define CP_WAIT(n)  asm volatile("cp.async.wait_group %0;\n" :: "n"(n) : "memory")

// ---------------- fp32 -> fp16 hi/lo split ----------------
__global__ void split_pair_kernel(const float* __restrict__ src,
                                  __half* __restrict__ hi,
                                  __half* __restrict__ lo, int n) {
    int i = blockIdx.x * blockDim.x + threadIdx.x;
    if (i < n) {
        __half h, l;
        split_fp16(src[i], h, l);
        hi[i] = h; lo[i] = l;
    }
}

// ---------------- fp32 -> fp16 single convert ----------------
__global__ void cvt_fp16_kernel(const float* __restrict__ src,
                                __half* __restrict__ dst, int n) {
    int i = blockIdx.x * blockDim.x + threadIdx.x;
    if (i < n) dst[i] = __float2half(src[i]);
}

// ---------------- bias add (final output epilogue) ----------------
__global__ void bias_add_kernel(float* __restrict__ C, const float* __restrict__ bias,
                                int N, int total) {
    int i = blockIdx.x * blockDim.x + threadIdx.x;
    if (i < total) C[i] += bias[i % N];
}

// ---------------- Tensor-core NT GEMM, fp16 A-compensated x2 ----------------
template <int BN>
__global__ __launch_bounds__(256, 2)
void gemm_fp16x2_nt(const __half* __restrict__ Ah, const __half* __restrict__ Al,
                    const __half* __restrict__ B,
                    float* __restrict__ C, int M, int N, int K) {
    constexpr int NF = BN / 32;
    __shared__ __half sA[2][2][128][40];
    __shared__ __half sB[2][BN][40];
    const int tid = threadIdx.x;
    const int bm = blockIdx.y * 128, bn = blockIdx.x * BN;
    const int warp = tid >> 5;
    const int wm = (warp & 3) * 32;
    const int wn = (warp >> 2) * (BN / 2);

    wmma::fragment<wmma::accumulator, 16, 16, 16, float> acc[2][NF];
#pragma unroll
    for (int i = 0; i < 2; i++)
#pragma unroll
        for (int j = 0; j < NF; j++) wmma::fill_fragment(acc[i][j], 0.f);

    const int lr = tid >> 2;
    const int lc = (tid & 3) * 8;

    auto load_stage = [&](int k0, int buf) {
#pragma unroll
        for (int r = 0; r < 128; r += 64) {
            const size_t aoff = (size_t)(bm + lr + r) * K + k0 + lc;
            CP_ASYNC16((unsigned)__cvta_generic_to_shared(&sA[buf][0][lr + r][lc]), Ah + aoff);
            CP_ASYNC16((unsigned)__cvta_generic_to_shared(&sA[buf][1][lr + r][lc]), Al + aoff);
        }
#pragma unroll
        for (int r = 0; r < BN; r += 64) {
            const size_t boff = (size_t)(bn + lr + r) * K + k0 + lc;
            CP_ASYNC16((unsigned)__cvta_generic_to_shared(&sB[buf][lr + r][lc]), B + boff);
        }
    };

    load_stage(0, 0);
    CP_COMMIT();

    const int nt = K >> 5;
    for (int kt = 0; kt < nt; kt++) {
        const int buf = kt & 1;
        if (kt + 1 < nt) {
            load_stage((kt + 1) << 5, buf ^ 1);
            CP_COMMIT();
            CP_WAIT(1);
        } else {
            CP_WAIT(0);
        }
        __syncthreads();
#pragma unroll
        for (int ks = 0; ks < 32; ks += 16) {
            wmma::fragment<wmma::matrix_a, 16, 16, 16, __half, wmma::row_major> ah[2], al[2];
#pragma unroll
            for (int i = 0; i < 2; i++) {
                wmma::load_matrix_sync(ah[i], &sA[buf][0][wm + 16 * i][ks], 40);
                wmma::load_matrix_sync(al[i], &sA[buf][1][wm + 16 * i][ks], 40);
            }
#pragma unroll
            for (int j = 0; j < NF; j++) {
                wmma::fragment<wmma::matrix_b, 16, 16, 16, __half, wmma::col_major> bf;
                wmma::load_matrix_sync(bf, &sB[buf][wn + 16 * j][ks], 40);
                wmma::mma_sync(acc[0][j], ah[0], bf, acc[0][j]);
                wmma::mma_sync(acc[1][j], ah[1], bf, acc[1][j]);
                wmma::mma_sync(acc[0][j], al[0], bf, acc[0][j]);
                wmma::mma_sync(acc[1][j], al[1], bf, acc[1][j]);
            }
        }
        __syncthreads();
    }
#pragma unroll
    for (int i = 0; i < 2; i++)
#pragma unroll
        for (int j = 0; j < NF; j++)
            wmma::store_matrix_sync(C + (size_t)(bm + wm + 16 * i) * N + bn + wn + 16 * j,
                                    acc[i][j], N, wmma::mem_row_major);
}

// ---------------- Depthwise causal conv (K=4) + SiLU + split (b1 fused) ----------------
__global__ void conv_silu_kernel(const float* __restrict__ conv_w,
                                 const float* __restrict__ b1) {
    int idx = blockIdx.x * blockDim.x + threadIdx.x;
    if (idx >= T_LEN * CONV_DIM) return;
    int t = idx / CONV_DIM;
    int c = idx % CONV_DIM;
    const float bias = b1[INTER + c];
    float acc = 0.f;
#pragma unroll
    for (int w = 0; w < KCONV; w++) {
        int ts = t - (KCONV - 1) + w;
        if (ts >= 0)
            acc = fmaf(g_zx[(size_t)ts * PROJ + INTER + c] + bias, conv_w[c * KCONV + w], acc);
    }
    float s = silu_f(acc);
    if (c < INTER) {
        g_x[(size_t)t * INTER + c] = s;
    } else if (c < INTER + N_STATE) {
        g_Bm16[t * N_STATE + (c - INTER)] = __float2half(s);
    } else {
        __half h, l; split_fp16(s, h, l);
        int o = t * N_STATE + (c - INTER - N_STATE);
        g_Ch[o] = h; g_Cl[o] = l;
    }
}

// ---------------- dt / g / Ls prep (b1 fused) ----------------
__global__ void prep_kernel(const float* __restrict__ dt_bias,
                            const float* __restrict__ A_log,
                            const float* __restrict__ L_param,
                            const float* __restrict__ b1) {
    int t = blockIdx.x;
    const float* row = g_zx + (size_t)t * PROJ + DT_OFF;
    const float* brow = b1 + DT_OFF;
    for (int i = threadIdx.x; i < H_HEADS; i += blockDim.x) {
        float d = softplus_f(row[i] + brow[i] + dt_bias[i]);
        g_dt[t * H_HEADS + i] = d;
        g_g[i * T_LEN + t] = -expf(A_log[i]) * d;
    }
    for (int i = threadIdx.x; i < H_HEADS * NL; i += blockDim.x) {
        g_Ls[(size_t)t * (H_HEADS * NL) + i] =
            softplus_f(L_param[i] * (row[H_HEADS + i] + brow[H_HEADS + i]));
    }
}

// ---------------- inclusive scan of g over t, per head ----------------
__global__ __launch_bounds__(1024)
void scan_kernel() {
    __shared__ float sh[T_LEN];
    int h = blockIdx.x;
    int t = threadIdx.x;
    sh[t] = g_g[h * T_LEN + t];
    __syncthreads();
    for (int off = 1; off < T_LEN; off <<= 1) {
        float add = (t >= off) ? sh[t - off] : 0.f;
        __syncthreads();
        sh[t] += add;
        __syncthreads();
    }
    g_cg[h * T_LEN + t] = sh[t];
}

// ---------------- Attention on tensor cores: per (head, t-tile of 64) ----------------
// w[t,s] = scores * exp(cg_t - cg_s) * Ls[t,lvl]  built in smem as fp16 hi/lo;
// v[s,p] = x[s,p]*dt[s] as fp16 hi/lo; y = w @ v via 3-pass compensated wmma.
// D residual is fused into gated_norm (not here).
__global__ __launch_bounds__(256)
void attn_tc_kernel(const int* __restrict__ lvl) {
    const int h = blockIdx.y;
    const int t0 = blockIdx.x * 64;
    __shared__ __half s_wh[64][72], s_wl[64][72];
    __shared__ __half s_vh[64][72], s_vl[64][72];
    __shared__ float s_cgt[64], s_cgs[64];
    __shared__ float s_Lst[64][16];
    const int tid = threadIdx.x;
    const int warp = tid >> 5;
    const int wm = (warp & 3) * 16;      // 4 warps along t
    const int wn = (warp >> 2) * 32;     // 2 warps along p

    if (tid < 64) s_cgt[tid] = g_cg[h * T_LEN + t0 + tid];
    for (int i = tid; i < 64 * NL; i += 256) {
        int r = i / NL, l = i % NL;
        s_Lst[r][l] = g_Ls[((size_t)(t0 + r) * H_HEADS + h) * NL + l];
    }

    wmma::fragment<wmma::accumulator, 16, 16, 16, float> acc[2];
    wmma::fill_fragment(acc[0], 0.f);
    wmma::fill_fragment(acc[1], 0.f);

    for (int s0 = 0; s0 <= t0; s0 += 64) {
        __syncthreads();   // protect smem from previous iteration's MMA reads
        if (s0 < t0) {
            float maxld = g_cg[h * T_LEN + t0] - g_cg[h * T_LEN + s0 + 63];
            if (maxld < -30.f) continue;
        }
        if (tid < 64) s_cgs[tid] = g_cg[h * T_LEN + s0 + tid];
        __syncthreads();
        // build w tile (fp16 pair)
        for (int i = tid; i < 64 * 64; i += 256) {
            int r = i >> 6, c = i & 63;
            int tg = t0 + r, sg = s0 + c;
            float w = 0.f;
            if (sg <= tg) {
                int L = lvl[(size_t)tg * T_LEN + sg];
                w = g_scores[(size_t)tg * T_LEN + sg] *
                    __expf(s_cgt[r] - s_cgs[c]) * s_Lst[r][L];
            }
            __half hh, ll; split_fp16(w, hh, ll);
            s_wh[r][c] = hh; s_wl[r][c] = ll;
        }
        // build v tile (fp16 pair)
        for (int i = tid; i < 64 * 64; i += 256) {
            int r = i >> 6, p = i & 63;
            float v = g_x[(size_t)(s0 + r) * INTER + h * P_DIM + p] *
                      g_dt[(s0 + r) * H_HEADS + h];
            __half hh, ll; split_fp16(v, hh, ll);
            s_vh[r][p] = hh; s_vl[r][p] = ll;
        }
        __syncthreads();
        // acc += w @ v  (3-pass compensated)
#pragma unroll
        for (int ks = 0; ks < 64; ks += 16) {
            wmma::fragment<wmma::matrix_a, 16, 16, 16, __half, wmma::row_major> ah, al;
            wmma::load_matrix_sync(ah, &s_wh[wm][ks], 72);
            wmma::load_matrix_sync(al, &s_wl[wm][ks], 72);
#pragma unroll
            for (int j = 0; j < 2; j++) {
                wmma::fragment<wmma::matrix_b, 16, 16, 16, __half, wmma::row_major> bh, bl;
                wmma::load_matrix_sync(bh, &s_vh[ks][wn + 16 * j], 72);
                wmma::load_matrix_sync(bl, &s_vl[ks][wn + 16 * j], 72);
                wmma::mma_sync(acc[j], ah, bh, acc[j]);
                wmma::mma_sync(acc[j], al, bh, acc[j]);
                wmma::mma_sync(acc[j], ah, bl, acc[j]);
            }
        }
    }
    // store (no residual here)
#pragma unroll
    for (int j = 0; j < 2; j++)
        wmma::store_matrix_sync(
            g_y + (size_t)(t0 + wm) * INTER + h * P_DIM + wn + 16 * j,
            acc[j], INTER, wmma::mem_row_major);
}

// ---------------- gated RMSNorm (b1 + D residual fused), fp16 hi/lo out ----------------
__global__ __launch_bounds__(256)
void gated_norm_kernel(const float* __restrict__ rmsw, const float* __restrict__ b1,
                       const float* __restrict__ Dp) {
    const int t = blockIdx.x;
    __shared__ float red[8];
    float vals[8];
    float local = 0.f;
#pragma unroll
    for (int i = 0; i < 8; i++) {
        int c = threadIdx.x + i * 256;
        float z = g_zx[(size_t)t * PROJ + c] + b1[c];
        float yv = g_y[(size_t)t * INTER + c] +
                   g_x[(size_t)t * INTER + c] * Dp[c >> 6];  // D residual
        float gv = yv * silu_f(z);
        vals[i] = gv;
        local = fmaf(gv, gv, local);
    }
#pragma unroll
    for (int off = 16; off > 0; off >>= 1)
        local += __shfl_xor_sync(0xffffffffu, local, off);
    if ((threadIdx.x & 31) == 0) red[threadIdx.x >> 5] = local;
    __syncthreads();
    if (threadIdx.x < 8) {
        float v = red[threadIdx.x];
#pragma unroll
        for (int off = 4; off > 0; off >>= 1)
            v += __shfl_xor_sync(0xffu, v, off);
        if (threadIdx.x == 0) red[0] = v;
    }
    __syncthreads();
    const float inv = rsqrtf(red[0] / (float)INTER + EPSNRM);
#pragma unroll
    for (int i = 0; i < 8; i++) {
        int c = threadIdx.x + i * 256;
        float v = vals[i] * inv * rmsw[c];
        __half h, l; split_fp16(v, h, l);
        g_ynh[(size_t)t * INTER + c] = h;
        g_ynl[(size_t)t * INTER + c] = l;
    }
}

// ---------------- Launch ----------------
extern "C" void kernel_launch(void* const* d_in, const int* in_sizes, int n_in,
                              void* d_out, int out_size) {
    const float* hs    = (const float*)d_in[0];
    const float* w1    = (const float*)d_in[1];
    const float* b1    = (const float*)d_in[2];
    const float* cw    = (const float*)d_in[3];
    const float* dtb   = (const float*)d_in[4];
    const float* alog  = (const float*)d_in[5];
    const float* lpar  = (const float*)d_in[6];
    const float* Dp    = (const float*)d_in[7];
    const float* rmsw  = (const float*)d_in[8];
    const float* w2    = (const float*)d_in[9];
    const float* b2    = (const float*)d_in[10];
    const int*   lvl   = (const int*)d_in[11];
    float* out = (float*)d_out;

    float *zx, *scores;
    __half *hsh, *hsl, *w1p, *w2p, *Bm16, *Ch, *Cl, *ynh, *ynl;
    cudaGetSymbolAddress((void**)&zx, g_zx);
    cudaGetSymbolAddress((void**)&scores, g_scores);
    cudaGetSymbolAddress((void**)&hsh, g_hsh);  cudaGetSymbolAddress((void**)&hsl, g_hsl);
    cudaGetSymbolAddress((void**)&w1p, g_w1);   cudaGetSymbolAddress((void**)&w2p, g_w2);
    cudaGetSymbolAddress((void**)&Bm16, g_Bm16);
    cudaGetSymbolAddress((void**)&Ch, g_Ch);    cudaGetSymbolAddress((void**)&Cl, g_Cl);
    cudaGetSymbolAddress((void**)&ynh, g_ynh);  cudaGetSymbolAddress((void**)&ynl, g_ynl);

    // 0) operand conversion
    split_pair_kernel<<<(T_LEN * HID + 255) / 256, 256>>>(hs, hsh, hsl, T_LEN * HID);
    cvt_fp16_kernel<<<(PROJ * HID + 255) / 256, 256>>>(w1, w1p, PROJ * HID);
    cvt_fp16_kernel<<<(HID * INTER + 255) / 256, 256>>>(w2, w2p, HID * INTER);

    // 1) in_proj
    gemm_fp16x2_nt<128><<<dim3(PROJ / 128, T_LEN / 128), 256>>>(hsh, hsl, w1p, zx,
                                                                T_LEN, PROJ, HID);

    // 2) conv + silu + split
    conv_silu_kernel<<<(T_LEN * CONV_DIM + 255) / 256, 256>>>(cw, b1);

    // 3) dt / g / Ls
    prep_kernel<<<T_LEN, 128>>>(dtb, alog, lpar, b1);

    // 4) cumsum of g per head
    scan_kernel<<<H_HEADS, 1024>>>();

    // 5) scores[t,s] = C[t]·B[s]
    gemm_fp16x2_nt<64><<<dim3(T_LEN / 64, T_LEN / 128), 256>>>(Ch, Cl, Bm16, scores,
                                                               T_LEN, T_LEN, N_STATE);

    // 6) attention (tensor-core w@v)
    attn_tc_kernel<<<dim3(T_LEN / 64, H_HEADS), 256>>>(lvl);

    // 7) gated RMSNorm (D residual + b1 fused)
    gated_norm_kernel<<<T_LEN, 256>>>(rmsw, b1, Dp);

    // 8) out_proj
    gemm_fp16x2_nt<64><<<dim3(HID / 64, T_LEN / 128), 256>>>(ynh, ynl, w2p, out,
                                                             T_LEN, HID, INTER);
    bias_add_kernel<<<(T_LEN * HID + 255) / 256, 256>>>(out, b2, HID, T_LEN * HID);
}